// round 11
// baseline (speedup 1.0000x reference)
#include <cuda_runtime.h>
#include <cstddef>

#define TT_STEPS 365
#define NB 4000
#define MM 4
#define LENF 15

// Scratch (allocation-free: __device__ globals)
__device__ float g_qsim[TT_STEPS * NB];   // mean-over-M runoff per (t, n)
__device__ float g_uh[LENF * NB];         // routing weights per (k, n)

#define STAGES 5                          // 365 % 5 == 0 -> compile-time stage idx
#define BSTRIDE 68                        // 64 floats + 4 pad -> conflict-free LDS
#define STAGE_FLOATS (8 * BSTRIDE)        // 544 floats = 2176 B per warp-stage
#define WARPS_PER_BLOCK 8                 // 2 warps per SMSP -> fills dep stalls
#define TOTAL_WARPS 500                   // 16000 chains / 32
#define SCAN_BLOCKS 63                    // ceil(500/8); last 4 warps idle
#define SCAN_SMEM (WARPS_PER_BLOCK * STAGES * STAGE_FLOATS * 4)  // 87040 B

__device__ __forceinline__ void cp_async16(unsigned smem_addr, const void* gptr) {
    asm volatile("cp.async.cg.shared.global [%0], [%1], 16;\n"
                 :: "r"(smem_addr), "l"(gptr));
}
__device__ __forceinline__ void cp_commit() {
    asm volatile("cp.async.commit_group;\n");
}
#define CP_WAIT_GROUP(nrem) asm volatile("cp.async.wait_group %0;\n" :: "n"(nrem))

// -------------------------------------------------------------------------
// Kernel 1: HBV scan. One thread per (n, m) chain; 16000 threads in 63
// blocks of 256 -> 2 warps per SMSP so dependency stalls of one warp are
// filled by the other. 5-stage cp.async ring, static stage indices.
// -------------------------------------------------------------------------
struct HBVState {
    float SNOWPACK, MELTWATER, SM, SUZ, SLZ;
};

__device__ __forceinline__ void hbv_step(HBVState& st,
                                         const float cur[14],
                                         float P, float Ta, float PET,
                                         int t, int n, int m) {
    const float BETA   = 1.0f   + 5.0f    * cur[0];
    const float FC     = 50.0f  + 950.0f  * cur[1];
    const float K0     = 0.05f  + 0.85f   * cur[2];
    const float K1     = 0.01f  + 0.49f   * cur[3];
    const float K2     = 0.001f + 0.199f  * cur[4];
    const float LP     = 0.2f   + 0.8f    * cur[5];
    const float PERC   =          10.0f   * cur[6];
    const float UZL    =          100.0f  * cur[7];
    const float TTp    = -2.5f  + 5.0f    * cur[8];
    const float CFMAX  = 0.5f   + 9.5f    * cur[9];
    const float CFR    =          0.1f    * cur[10];
    const float CWH    =          0.2f    * cur[11];
    const float BETAET = 0.3f   + 4.7f    * cur[12];
    const float Cc     =                    cur[13];

    const float RAIN = (Ta >= TTp) ? P : 0.0f;
    const float SNOW = (Ta <  TTp) ? P : 0.0f;
    st.SNOWPACK += SNOW;
    const float melt = fminf(fmaxf(CFMAX * (Ta - TTp), 0.0f), st.SNOWPACK);
    st.MELTWATER += melt;
    st.SNOWPACK = fmaxf(st.SNOWPACK - melt, 1e-5f);
    const float refreeze = fminf(fmaxf(CFR * CFMAX * (TTp - Ta), 0.0f), st.MELTWATER);
    st.SNOWPACK += refreeze;
    st.MELTWATER = fmaxf(st.MELTWATER - refreeze, 1e-5f);
    const float tosoil = fmaxf(st.MELTWATER - CWH * st.SNOWPACK, 0.0f);
    st.MELTWATER = fmaxf(st.MELTWATER - tosoil, 1e-5f);

    const float rFC   = __fdividef(1.0f, FC);
    const float rLPFC = __fdividef(1.0f, LP * FC);

    float soil_wet = __expf(BETA * __logf(st.SM * rFC));
    soil_wet = fminf(fmaxf(soil_wet, 0.0f), 1.0f);
    const float recharge = (RAIN + tosoil) * soil_wet;
    st.SM = st.SM + RAIN + tosoil - recharge;
    const float excess = fmaxf(st.SM - FC, 0.0f);
    st.SM = fmaxf(st.SM - excess, 1e-5f);

    float evapfactor = __expf(BETAET * __logf(st.SM * rLPFC));
    evapfactor = fminf(fmaxf(evapfactor, 0.0f), 1.0f);
    const float ETact = fminf(st.SM, PET * evapfactor);
    st.SM = fmaxf(st.SM - ETact, 1e-5f);

    const float capillary = fminf(st.SLZ, Cc * st.SLZ * (1.0f - fminf(st.SM * rFC, 1.0f)));
    st.SM += capillary;
    st.SLZ = fmaxf(st.SLZ - capillary, 1e-5f);

    st.SUZ += recharge + excess;
    const float PERCa = fminf(st.SUZ, PERC);
    st.SUZ -= PERCa;
    const float Q0 = K0 * fmaxf(st.SUZ - UZL, 0.0f);
    st.SUZ -= Q0;
    const float Q1 = K1 * st.SUZ;
    st.SUZ -= Q1;
    st.SLZ += PERCa;
    const float Q2 = K2 * st.SLZ;
    st.SLZ -= Q2;

    float q = Q0 + Q1 + Q2;
    q += __shfl_xor_sync(0xffffffffu, q, 1);
    q += __shfl_xor_sync(0xffffffffu, q, 2);
    if (m == 0)
        g_qsim[(size_t)t * NB + n] = 0.25f * q;
}

__global__ void __launch_bounds__(256)
hbv_scan_kernel(const float* __restrict__ x,        // (T, N, 3)
                const float* __restrict__ praw) {   // (T, N, 16, M)
    extern __shared__ __align__(16) float sp[];     // [8][STAGES][STAGE_FLOATS]

    const int lane = threadIdx.x & 31;
    const int wrp  = threadIdx.x >> 5;                       // 0..7
    const int w    = blockIdx.x * WARPS_PER_BLOCK + wrp;     // global warp id
    if (w >= TOTAL_WARPS) return;                            // 4 idle warps

    const int n0      = w * 8;                 // warp's first basin
    const int n_local = lane >> 2;             // basin within warp (0..7)
    const int n       = n0 + n_local;          // consumer: basin
    const int m       = lane & 3;              // consumer: ensemble member

    float* swarp = sp + wrp * (STAGES * STAGE_FLOATS);

    // producer: lane L copies 16-byte chunks c = j*32 + L (j = 0..3) of the
    // warp's 2048-byte param block
    unsigned sdst[4];
    const float* gsrc[4];
#pragma unroll
    for (int j = 0; j < 4; ++j) {
        const int c = j * 32 + lane;
        sdst[j] = (unsigned)__cvta_generic_to_shared(
                      swarp + (c >> 4) * BSTRIDE + (c & 15) * 4);
        gsrc[j] = praw + (size_t)n0 * 64 + (size_t)c * 4;
    }
    const unsigned stage_bytes = STAGE_FLOATS * 4;

    const float* xbase = x + (size_t)n * 3;
    const float* prd   = swarp + n_local * BSTRIDE + m;

    HBVState st = {0.001f, 0.001f, 0.001f, 0.001f, 0.001f};

    float fb[STAGES][3];   // statically indexed everywhere below

    // prologue: fill 5 stages with t = 0..4
#pragma unroll
    for (int s = 0; s < STAGES; ++s) {
        const size_t poff = (size_t)s * (NB * 64);
#pragma unroll
        for (int j = 0; j < 4; ++j)
            cp_async16(sdst[j] + s * stage_bytes, gsrc[j] + poff);
        cp_commit();
        const size_t xoff = (size_t)s * (NB * 3);
#pragma unroll
        for (int c = 0; c < 3; ++c)
            fb[s][c] = __ldg(xbase + xoff + c);
    }

    // main loop: 73 iterations x 5 statically-staged steps
    for (int tb = 0; tb < TT_STEPS; tb += STAGES) {
#pragma unroll
        for (int s = 0; s < STAGES; ++s) {
            const int t = tb + s;

            CP_WAIT_GROUP(STAGES - 1);   // oldest group (stage s) complete
            __syncwarp();

            float cur[14];
            const float* ps = prd + s * STAGE_FLOATS;
#pragma unroll
            for (int i = 0; i < 14; ++i)
                cur[i] = ps[i * 4];
            const float P   = fb[s][0];
            const float Ta  = fb[s][1];
            const float PET = fb[s][2];

            // refill stage s with step t+5 (stage s reads finished at t-1;
            // this step's syncwarp ordered them before these writes)
            {
                const int tn = (t + STAGES < TT_STEPS) ? (t + STAGES) : (TT_STEPS - 1);
                const size_t poff = (size_t)tn * (NB * 64);
#pragma unroll
                for (int j = 0; j < 4; ++j)
                    cp_async16(sdst[j] + s * stage_bytes, gsrc[j] + poff);
                cp_commit();
                const size_t xoff = (size_t)tn * (NB * 3);
#pragma unroll
                for (int c = 0; c < 3; ++c)
                    fb[s][c] = __ldg(xbase + xoff + c);
            }

            hbv_step(st, cur, P, Ta, PET, t, n, m);
        }
    }
}

// -------------------------------------------------------------------------
// Kernel 2: gamma unit-hydrograph weights per basin (normalized).
// -------------------------------------------------------------------------
__global__ void uh_kernel(const float* __restrict__ conv) {
    const int n = blockIdx.x * blockDim.x + threadIdx.x;
    if (n >= NB) return;
    const float a = conv[n * 2 + 0] * 2.9f;
    const float b = conv[n * 2 + 1] * 6.5f;
    const float aa    = fmaxf(a, 0.0f) + 0.1f;
    const float theta = fmaxf(b, 0.0f) + 0.5f;
    const float lg = lgammaf(aa);
    const float lt = logf(theta);
    const float rth = 1.0f / theta;

    float w[LENF];
    float s = 0.0f;
#pragma unroll
    for (int k = 0; k < LENF; ++k) {
        const float tt = 0.5f + (float)k;
        w[k] = expf(-lg - aa * lt + (aa - 1.0f) * logf(tt) - tt * rth);
        s += w[k];
    }
    const float rs = 1.0f / s;
#pragma unroll
    for (int k = 0; k < LENF; ++k)
        g_uh[k * NB + n] = w[k] * rs;
}

// -------------------------------------------------------------------------
// Kernel 3: 15-tap causal FIR routing. One thread per (t, n) output.
// -------------------------------------------------------------------------
__global__ void rout_kernel(float* __restrict__ out) {
    const int idx = blockIdx.x * blockDim.x + threadIdx.x;
    if (idx >= TT_STEPS * NB) return;
    const int t = idx / NB;
    const int n = idx - t * NB;

    float acc = 0.0f;
#pragma unroll
    for (int k = 0; k < LENF; ++k) {
        if (k <= t)
            acc += __ldg(&g_uh[k * NB + n]) * __ldg(&g_qsim[(size_t)(t - k) * NB + n]);
    }
    out[idx] = acc;
}

// -------------------------------------------------------------------------
extern "C" void kernel_launch(void* const* d_in, const int* in_sizes, int n_in,
                              void* d_out, int out_size) {
    const float* x    = (const float*)d_in[0];   // (365, 4000, 3)
    const float* praw = (const float*)d_in[1];   // (365, 4000, 16, 4)
    const float* conv = (const float*)d_in[2];   // (4000, 2)
    float* out = (float*)d_out;                  // (365, 4000)

    // 87 KB dynamic smem (> 48 KB default): opt in (idempotent, capture-safe)
    cudaFuncSetAttribute(hbv_scan_kernel,
                         cudaFuncAttributeMaxDynamicSharedMemorySize, SCAN_SMEM);

    hbv_scan_kernel<<<SCAN_BLOCKS, 256, SCAN_SMEM>>>(x, praw);
    uh_kernel<<<(NB + 127) / 128, 128>>>(conv);
    rout_kernel<<<(TT_STEPS * NB + 255) / 256, 256>>>(out);
}

// round 12
// speedup vs baseline: 1.2726x; 1.2726x over previous
#include <cuda_runtime.h>
#include <cstddef>

#define TT_STEPS 365
#define NB 4000
#define MM 4
#define LENF 15

// Scratch (allocation-free: __device__ globals)
__device__ float g_qsim[TT_STEPS * NB];   // mean-over-M runoff per (t, n)
__device__ float g_uh[LENF * NB];         // routing weights per (k, n)

#define SPB 5                             // steps per smem buffer
#define BSTRIDE 68                        // 64 floats + 4 pad -> conflict-free LDS
#define STAGE_FLOATS (8 * BSTRIDE)        // 544 floats per step per warp
#define BUF_FLOATS (SPB * STAGE_FLOATS)   // 2720 floats per buffer
#define WARP_SMEM (2 * BUF_FLOATS)        // two buffers per warp
#define SCAN_SMEM (4 * WARP_SMEM * 4)     // 4 warps * 21760 B = 87040 B

__device__ __forceinline__ void cp_async16(unsigned smem_addr, const void* gptr) {
    asm volatile("cp.async.cg.shared.global [%0], [%1], 16;\n"
                 :: "r"(smem_addr), "l"(gptr));
}
__device__ __forceinline__ void cp_commit() {
    asm volatile("cp.async.commit_group;\n");
}
#define CP_WAIT_GROUP(nrem) asm volatile("cp.async.wait_group %0;\n" :: "n"(nrem))

// -------------------------------------------------------------------------
// Kernel 1: HBV scan. One thread per (n, m) chain; 16000 threads, 125
// blocks x 128 -> 1 warp per SMSP on every SM (wall-optimal; R10 showed
// 2 warps/SMSP on half the SMs raises the wall).
// KEY CHANGE: barriers only once per 5 steps. Two 5-step smem buffers,
// each filled by ONE cp.async group; the 5-step compute body is a
// barrier-free region so ptxas can interleave instructions across
// timesteps (fill dependency bubbles of step t with work of step t+1).
// -------------------------------------------------------------------------
struct HBVState {
    float SNOWPACK, MELTWATER, SM, SUZ, SLZ;
};

__device__ __forceinline__ void hbv_step(HBVState& st,
                                         const float cur[14],
                                         float P, float Ta, float PET,
                                         int t, int n, int m) {
    const float BETA   = 1.0f   + 5.0f    * cur[0];
    const float FC     = 50.0f  + 950.0f  * cur[1];
    const float K0     = 0.05f  + 0.85f   * cur[2];
    const float K1     = 0.01f  + 0.49f   * cur[3];
    const float K2     = 0.001f + 0.199f  * cur[4];
    const float LP     = 0.2f   + 0.8f    * cur[5];
    const float PERC   =          10.0f   * cur[6];
    const float UZL    =          100.0f  * cur[7];
    const float TTp    = -2.5f  + 5.0f    * cur[8];
    const float CFMAX  = 0.5f   + 9.5f    * cur[9];
    const float CFR    =          0.1f    * cur[10];
    const float CWH    =          0.2f    * cur[11];
    const float BETAET = 0.3f   + 4.7f    * cur[12];
    const float Cc     =                    cur[13];

    const float RAIN = (Ta >= TTp) ? P : 0.0f;
    const float SNOW = (Ta <  TTp) ? P : 0.0f;
    st.SNOWPACK += SNOW;
    const float melt = fminf(fmaxf(CFMAX * (Ta - TTp), 0.0f), st.SNOWPACK);
    st.MELTWATER += melt;
    st.SNOWPACK = fmaxf(st.SNOWPACK - melt, 1e-5f);
    const float refreeze = fminf(fmaxf(CFR * CFMAX * (TTp - Ta), 0.0f), st.MELTWATER);
    st.SNOWPACK += refreeze;
    st.MELTWATER = fmaxf(st.MELTWATER - refreeze, 1e-5f);
    const float tosoil = fmaxf(st.MELTWATER - CWH * st.SNOWPACK, 0.0f);
    st.MELTWATER = fmaxf(st.MELTWATER - tosoil, 1e-5f);

    const float rFC   = __fdividef(1.0f, FC);
    const float rLPFC = __fdividef(1.0f, LP * FC);

    float soil_wet = __expf(BETA * __logf(st.SM * rFC));
    soil_wet = fminf(fmaxf(soil_wet, 0.0f), 1.0f);
    const float recharge = (RAIN + tosoil) * soil_wet;
    st.SM = st.SM + RAIN + tosoil - recharge;
    const float excess = fmaxf(st.SM - FC, 0.0f);
    st.SM = fmaxf(st.SM - excess, 1e-5f);

    float evapfactor = __expf(BETAET * __logf(st.SM * rLPFC));
    evapfactor = fminf(fmaxf(evapfactor, 0.0f), 1.0f);
    const float ETact = fminf(st.SM, PET * evapfactor);
    st.SM = fmaxf(st.SM - ETact, 1e-5f);

    const float capillary = fminf(st.SLZ, Cc * st.SLZ * (1.0f - fminf(st.SM * rFC, 1.0f)));
    st.SM += capillary;
    st.SLZ = fmaxf(st.SLZ - capillary, 1e-5f);

    st.SUZ += recharge + excess;
    const float PERCa = fminf(st.SUZ, PERC);
    st.SUZ -= PERCa;
    const float Q0 = K0 * fmaxf(st.SUZ - UZL, 0.0f);
    st.SUZ -= Q0;
    const float Q1 = K1 * st.SUZ;
    st.SUZ -= Q1;
    st.SLZ += PERCa;
    const float Q2 = K2 * st.SLZ;
    st.SLZ -= Q2;

    float q = Q0 + Q1 + Q2;
    q += __shfl_xor_sync(0xffffffffu, q, 1);
    q += __shfl_xor_sync(0xffffffffu, q, 2);
    if (m == 0)
        g_qsim[(size_t)t * NB + n] = 0.25f * q;
}

__global__ void __launch_bounds__(128)
hbv_scan_kernel(const float* __restrict__ x,        // (T, N, 3)
                const float* __restrict__ praw) {   // (T, N, 16, M)
    extern __shared__ __align__(16) float sp[];     // [4 warps][2][BUF_FLOATS]

    const int lane = threadIdx.x & 31;
    const int wrp  = threadIdx.x >> 5;
    const int tid  = blockIdx.x * 128 + threadIdx.x;   // exactly 16000

    const int n       = tid >> 2;        // consumer: basin
    const int m       = tid & 3;         // consumer: ensemble member
    const int n_local = lane >> 2;       // basin within warp (0..7)
    const int n0      = (tid >> 5) * 8;  // warp's first basin

    float* wbase = sp + wrp * WARP_SMEM;

    // producer: lane L copies 16-byte chunks c = j*32 + L (j = 0..3) of the
    // warp's 2048-byte param block (per step)
    unsigned sdst[4];                    // chunk offsets within buffer 0, step 0
    const float* gsrc[4];
#pragma unroll
    for (int j = 0; j < 4; ++j) {
        const int c = j * 32 + lane;
        sdst[j] = (unsigned)__cvta_generic_to_shared(
                      wbase + (c >> 4) * BSTRIDE + (c & 15) * 4);
        gsrc[j] = praw + (size_t)n0 * 64 + (size_t)c * 4;
    }
    const unsigned stage_bytes = STAGE_FLOATS * 4;
    const unsigned buf_bytes   = BUF_FLOATS * 4;

    const float* xbase = x + (size_t)n * 3;
    const float* prd0  = wbase + n_local * BSTRIDE + m;            // buffer 0
    const float* prd1  = prd0 + BUF_FLOATS;                        // buffer 1

    HBVState st = {0.001f, 0.001f, 0.001f, 0.001f, 0.001f};

    float fb0[SPB][3], fb1[SPB][3];      // forcings, statically indexed

    // ---- fill helpers (inlined; one commit group per 5-step buffer) ----
#define FILL_BUF(BSEL, TBASE, FB)                                          \
    {                                                                      \
        _Pragma("unroll")                                                  \
        for (int s_ = 0; s_ < SPB; ++s_) {                                 \
            const int tn_ = ((TBASE) + s_ < TT_STEPS) ? (TBASE) + s_       \
                                                      : (TT_STEPS - 1);    \
            const size_t poff_ = (size_t)tn_ * (NB * 64);                  \
            _Pragma("unroll")                                              \
            for (int j_ = 0; j_ < 4; ++j_)                                 \
                cp_async16(sdst[j_] + (BSEL) * buf_bytes                   \
                                    + s_ * stage_bytes,                    \
                           gsrc[j_] + poff_);                              \
            const size_t xoff_ = (size_t)tn_ * (NB * 3);                   \
            _Pragma("unroll")                                              \
            for (int c_ = 0; c_ < 3; ++c_)                                 \
                FB[s_][c_] = __ldg(xbase + xoff_ + c_);                    \
        }                                                                  \
        cp_commit();                                                       \
    }

#define PROCESS_BUF(PRD, TBASE, FB)                                        \
    {                                                                      \
        _Pragma("unroll")                                                  \
        for (int s_ = 0; s_ < SPB; ++s_) {                                 \
            float cur_[14];                                                \
            const float* ps_ = (PRD) + s_ * STAGE_FLOATS;                  \
            _Pragma("unroll")                                              \
            for (int i_ = 0; i_ < 14; ++i_)                                \
                cur_[i_] = ps_[i_ * 4];                                    \
            hbv_step(st, cur_, FB[s_][0], FB[s_][1], FB[s_][2],            \
                     (TBASE) + s_, n, m);                                  \
        }                                                                  \
    }

    // prologue: buffer0 <- t 0..4 (group0), buffer1 <- t 5..9 (group1)
    FILL_BUF(0, 0, fb0);
    FILL_BUF(1, SPB, fb1);

    // 36 iterations x 10 steps + 5-step tail = 365
    for (int i = 0; i < 36; ++i) {
        const int tb = i * 10;

        CP_WAIT_GROUP(1);     // buffer0's group done (1 outstanding allowed)
        __syncwarp();
        PROCESS_BUF(prd0, tb, fb0);            // steps tb .. tb+4
        FILL_BUF(0, tb + 10, fb0);             // refill buffer0

        CP_WAIT_GROUP(1);     // buffer1's group done
        __syncwarp();
        PROCESS_BUF(prd1, tb + SPB, fb1);      // steps tb+5 .. tb+9
        FILL_BUF(1, tb + 15, fb1);             // refill buffer1
    }

    // tail: steps 360..364 live in buffer0 (refilled at i=35)
    CP_WAIT_GROUP(1);
    __syncwarp();
    PROCESS_BUF(prd0, 360, fb0);
    CP_WAIT_GROUP(0);         // drain before exit
}

// -------------------------------------------------------------------------
// Kernel 2: gamma unit-hydrograph weights per basin (normalized).
// -------------------------------------------------------------------------
__global__ void uh_kernel(const float* __restrict__ conv) {
    const int n = blockIdx.x * blockDim.x + threadIdx.x;
    if (n >= NB) return;
    const float a = conv[n * 2 + 0] * 2.9f;
    const float b = conv[n * 2 + 1] * 6.5f;
    const float aa    = fmaxf(a, 0.0f) + 0.1f;
    const float theta = fmaxf(b, 0.0f) + 0.5f;
    const float lg = lgammaf(aa);
    const float lt = logf(theta);
    const float rth = 1.0f / theta;

    float w[LENF];
    float s = 0.0f;
#pragma unroll
    for (int k = 0; k < LENF; ++k) {
        const float tt = 0.5f + (float)k;
        w[k] = expf(-lg - aa * lt + (aa - 1.0f) * logf(tt) - tt * rth);
        s += w[k];
    }
    const float rs = 1.0f / s;
#pragma unroll
    for (int k = 0; k < LENF; ++k)
        g_uh[k * NB + n] = w[k] * rs;
}

// -------------------------------------------------------------------------
// Kernel 3: 15-tap causal FIR routing. One thread per (t, n) output.
// -------------------------------------------------------------------------
__global__ void rout_kernel(float* __restrict__ out) {
    const int idx = blockIdx.x * blockDim.x + threadIdx.x;
    if (idx >= TT_STEPS * NB) return;
    const int t = idx / NB;
    const int n = idx - t * NB;

    float acc = 0.0f;
#pragma unroll
    for (int k = 0; k < LENF; ++k) {
        if (k <= t)
            acc += __ldg(&g_uh[k * NB + n]) * __ldg(&g_qsim[(size_t)(t - k) * NB + n]);
    }
    out[idx] = acc;
}

// -------------------------------------------------------------------------
extern "C" void kernel_launch(void* const* d_in, const int* in_sizes, int n_in,
                              void* d_out, int out_size) {
    const float* x    = (const float*)d_in[0];   // (365, 4000, 3)
    const float* praw = (const float*)d_in[1];   // (365, 4000, 16, 4)
    const float* conv = (const float*)d_in[2];   // (4000, 2)
    float* out = (float*)d_out;                  // (365, 4000)

    // 87 KB dynamic smem (> 48 KB default): opt in (idempotent, capture-safe)
    cudaFuncSetAttribute(hbv_scan_kernel,
                         cudaFuncAttributeMaxDynamicSharedMemorySize, SCAN_SMEM);

    hbv_scan_kernel<<<125, 128, SCAN_SMEM>>>(x, praw);
    uh_kernel<<<(NB + 127) / 128, 128>>>(conv);
    rout_kernel<<<(TT_STEPS * NB + 255) / 256, 256>>>(out);
}